// round 1
// baseline (speedup 1.0000x reference)
#include <cuda_runtime.h>

#define D      256
#define TILE_P 64
#define TILE_V 128
#define TK     16

__device__ float g_v2[4096];

// ---------------------------------------------------------------------------
// v2[v] = sum_k vocab[v][k]^2   (one warp per vocab row)
// ---------------------------------------------------------------------------
__global__ void v2_kernel(const float* __restrict__ vocab, int V) {
    int v = blockIdx.x * 8 + (threadIdx.x >> 5);
    int lane = threadIdx.x & 31;
    if (v >= V) return;
    const float* row = vocab + v * D;
    float s = 0.f;
#pragma unroll
    for (int k = lane; k < D; k += 32) { float x = row[k]; s += x * x; }
#pragma unroll
    for (int o = 16; o > 0; o >>= 1) s += __shfl_down_sync(0xffffffffu, s, o);
    if (lane == 0) g_v2[v] = s;
}

// ---------------------------------------------------------------------------
// patchify: images[b, ph*16+i, pw*16+j] -> patches[b, ph*16+pw, i*16+j]
// (H = W = 256, patch 16 -> pure permutation copy, exact)
// ---------------------------------------------------------------------------
__global__ void patchify_kernel(const float* __restrict__ images,
                                float* __restrict__ patches, int total) {
    int idx = blockIdx.x * blockDim.x + threadIdx.x;
    if (idx >= total) return;
    int d = idx & 255;
    int n = (idx >> 8) & 255;
    int b = idx >> 16;
    int ph = n >> 4, pw = n & 15;
    int i = d >> 4, j = d & 15;
    patches[idx] = images[(b << 16) + ((ph * 16 + i) << 8) + pw * 16 + j];
}

// ---------------------------------------------------------------------------
// Fused score GEMM + argmin.
// Block: 256 threads = (tx 0..15 vocab-dir) x (ty 0..15 patch-dir).
// Tile:  64 patches x 128 vocab, K-chunks of 16. Per-thread 4x8 register tile.
// score(p, v) = v2[v] - 2 * dot(P[p], V[v])   (x2 row-constant dropped)
// ---------------------------------------------------------------------------
__global__ __launch_bounds__(256, 2)
void argmin_kernel(const float* __restrict__ patches,
                   const float* __restrict__ vocab,
                   float* __restrict__ tokens, int V) {
    __shared__ union SMem {
        struct {
            float a[TK][TILE_P + 4];   // 68 floats/row -> 272B (16B aligned)
            float b[TK][TILE_V + 4];   // 132 floats/row -> 528B (16B aligned)
            float v2[TILE_V];
        } ld;
        struct {
            float s[TILE_P][16];
            int   idx[TILE_P][16];
        } red;
    } sm;

    const int tid = threadIdx.x;
    const int tx = tid & 15;        // vocab direction
    const int ty = tid >> 4;        // patch direction
    const int p0 = blockIdx.x * TILE_P;

    // loader mappings
    const int la_p = tid >> 2;          // 0..63   (A: 1 float4 per thread)
    const int la_q = tid & 3;           // 0..3    (which float4 of the 16-k chunk)
    const int lb_v = tid >> 1;          // 0..127  (B: 2 float4 per thread)
    const int lb_h = (tid & 1) * 8;     // 0 or 8

    float best[4];
    int   bidx[4];
#pragma unroll
    for (int i = 0; i < 4; i++) { best[i] = 3.4e38f; bidx[i] = 0; }

    for (int v0 = 0; v0 < V; v0 += TILE_V) {
        float acc[4][8];
#pragma unroll
        for (int i = 0; i < 4; i++)
#pragma unroll
            for (int j = 0; j < 8; j++) acc[i][j] = 0.f;

#pragma unroll 1
        for (int kt = 0; kt < D / TK; kt++) {
            __syncthreads();   // prior compute / v2 reads finished
            // load A chunk (transposed into [k][p])
            {
                const float4 va = *(const float4*)&patches[(p0 + la_p) * D + kt * TK + la_q * 4];
                sm.ld.a[la_q * 4 + 0][la_p] = va.x;
                sm.ld.a[la_q * 4 + 1][la_p] = va.y;
                sm.ld.a[la_q * 4 + 2][la_p] = va.z;
                sm.ld.a[la_q * 4 + 3][la_p] = va.w;
            }
            // load B chunk (transposed into [k][v])
            {
                const float* vr = &vocab[(v0 + lb_v) * D + kt * TK + lb_h];
                const float4 vb0 = *(const float4*)(vr + 0);
                const float4 vb1 = *(const float4*)(vr + 4);
                sm.ld.b[lb_h + 0][lb_v] = vb0.x;
                sm.ld.b[lb_h + 1][lb_v] = vb0.y;
                sm.ld.b[lb_h + 2][lb_v] = vb0.z;
                sm.ld.b[lb_h + 3][lb_v] = vb0.w;
                sm.ld.b[lb_h + 4][lb_v] = vb1.x;
                sm.ld.b[lb_h + 5][lb_v] = vb1.y;
                sm.ld.b[lb_h + 6][lb_v] = vb1.z;
                sm.ld.b[lb_h + 7][lb_v] = vb1.w;
            }
            if (kt == 0 && tid < TILE_V) sm.ld.v2[tid] = g_v2[v0 + tid];
            __syncthreads();

#pragma unroll
            for (int kk = 0; kk < TK; kk++) {
                const float4 av = *(const float4*)&sm.ld.a[kk][ty * 4];
                const float4 b0 = *(const float4*)&sm.ld.b[kk][tx * 8];
                const float4 b1 = *(const float4*)&sm.ld.b[kk][tx * 8 + 4];
                const float aa[4] = {av.x, av.y, av.z, av.w};
                const float bb[8] = {b0.x, b0.y, b0.z, b0.w, b1.x, b1.y, b1.z, b1.w};
#pragma unroll
                for (int i = 0; i < 4; i++)
#pragma unroll
                    for (int j = 0; j < 8; j++)
                        acc[i][j] += aa[i] * bb[j];
            }
        }

        // running argmin update (vv strictly ascending within thread)
#pragma unroll
        for (int j = 0; j < 8; j++) {
            const int vv = v0 + tx * 8 + j;
            const float vsq = sm.ld.v2[tx * 8 + j];
#pragma unroll
            for (int i = 0; i < 4; i++) {
                const float s = vsq - 2.f * acc[i][j];
                if (s < best[i] || (s == best[i] && vv < bidx[i])) {
                    best[i] = s; bidx[i] = vv;
                }
            }
        }
    }

    __syncthreads();   // all ld-union readers done before red-union reuse
#pragma unroll
    for (int i = 0; i < 4; i++) {
        sm.red.s[ty * 4 + i][tx] = best[i];
        sm.red.idx[ty * 4 + i][tx] = bidx[i];
    }
    __syncthreads();
    if (tid < TILE_P) {
        float bs = sm.red.s[tid][0];
        int   bi = sm.red.idx[tid][0];
#pragma unroll
        for (int t = 1; t < 16; t++) {
            const float s = sm.red.s[tid][t];
            const int   id = sm.red.idx[tid][t];
            if (s < bs || (s == bs && id < bi)) { bs = s; bi = id; }
        }
        tokens[p0 + tid] = (float)bi;
    }
}

// ---------------------------------------------------------------------------
extern "C" void kernel_launch(void* const* d_in, const int* in_sizes, int n_in,
                              void* d_out, int out_size) {
    const float* images = (const float*)d_in[0];   // [64, 256, 256]
    const float* vocab  = (const float*)d_in[1];   // [4096, 256]
    float* out = (float*)d_out;

    const int npix = in_sizes[0];          // 64*256*256 = 4194304
    const int V    = in_sizes[1] / D;      // 4096
    const int NP   = npix / D;             // 16384 patches

    float* patches = out;                  // [NP, 256]
    float* tokens  = out + npix;           // [NP] as float

    v2_kernel<<<(V + 7) / 8, 256>>>(vocab, V);
    patchify_kernel<<<(npix + 255) / 256, 256>>>(images, patches, npix);
    argmin_kernel<<<NP / TILE_P, 256>>>(patches, vocab, tokens, V);
}

// round 3
// speedup vs baseline: 4.6780x; 4.6780x over previous
#include <cuda_runtime.h>
#include <cstdint>

#define D_DIM   256
#define NPATCH  16384
#define VOCAB   4096

#define TILE_M  128
#define TILE_N  256
#define NT      (VOCAB / TILE_N)   // 16
#define KCH     8                  // 32-k chunks per N-tile
#define NSTEPS  (NT * KCH)         // 128

#define SA_F    (TILE_M * D_DIM)   // 32768 floats (A resident)
#define SB_F    (TILE_N * 32)      // 8192 floats per stage
#define SMEM_F  (SA_F + 2 * SB_F + VOCAB)          // 53248 floats
#define SMEM_BYTES (SMEM_F * 4)                    // 212992 B

__device__ float g_v2[VOCAB];
__device__ float g_pperm[NPATCH * D_DIM];
__device__ float g_vperm[VOCAB * D_DIM];

#define CP_ASYNC16(dst, src) \
    asm volatile("cp.async.cg.shared.global [%0], [%1], 16;" :: "r"((uint32_t)(dst)), "l"(src))
#define CP_COMMIT() asm volatile("cp.async.commit_group;" ::: "memory")

__device__ __forceinline__ void mma8(float* c, float a0, float a1, float a2, float a3,
                                     float b0, float b1) {
    asm("mma.sync.aligned.m16n8k8.row.col.f32.tf32.tf32.f32 "
        "{%0,%1,%2,%3}, {%4,%5,%6,%7}, {%8,%9}, {%0,%1,%2,%3};"
        : "+f"(c[0]), "+f"(c[1]), "+f"(c[2]), "+f"(c[3])
        : "r"(__float_as_uint(a0)), "r"(__float_as_uint(a1)),
          "r"(__float_as_uint(a2)), "r"(__float_as_uint(a3)),
          "r"(__float_as_uint(b0)), "r"(__float_as_uint(b1)));
}

// ---------------------------------------------------------------------------
// prep kernels
// ---------------------------------------------------------------------------
__global__ void v2_kernel(const float* __restrict__ vocab, int V) {
    int v = blockIdx.x * 8 + (threadIdx.x >> 5);
    int lane = threadIdx.x & 31;
    if (v >= V) return;
    const float* row = vocab + v * D_DIM;
    float s = 0.f;
#pragma unroll
    for (int k = lane; k < D_DIM; k += 32) { float x = row[k]; s += x * x; }
#pragma unroll
    for (int o = 16; o > 0; o >>= 1) s += __shfl_down_sync(0xffffffffu, s, o);
    if (lane == 0) g_v2[v] = s;
}

// within each 16-float k-group, element at col c = q*4+t is stored at slot t*4+q
__device__ __forceinline__ int kperm(int c) {
    return (c & ~15) + ((c & 3) << 2) + ((c >> 2) & 3);
}

__global__ void patchify_perm_kernel(const float* __restrict__ images,
                                     float* __restrict__ patches, int total) {
    int idx = blockIdx.x * blockDim.x + threadIdx.x;
    if (idx >= total) return;
    int d = idx & 255, n = (idx >> 8) & 255, b = idx >> 16;
    int ph = n >> 4, pw = n & 15, i = d >> 4, j = d & 15;
    float x = images[(b << 16) + ((ph * 16 + i) << 8) + pw * 16 + j];
    patches[idx] = x;
    g_pperm[(idx & ~255) + kperm(d)] = x;
}

__global__ void vocab_perm_kernel(const float* __restrict__ vocab, int total) {
    int idx = blockIdx.x * blockDim.x + threadIdx.x;
    if (idx >= total) return;
    g_vperm[(idx & ~255) + kperm(idx & 255)] = vocab[idx];
}

// ---------------------------------------------------------------------------
// fused tf32 mma.sync GEMM + best2 argmin + exact fp32 rescue
// ---------------------------------------------------------------------------
__global__ __launch_bounds__(256, 1)
void vq_mma_kernel(const float* __restrict__ patches,
                   const float* __restrict__ vocab,
                   float* __restrict__ tokens) {
    extern __shared__ float sm[];
    float* smA  = sm;                   // [128][256] floats, 16B-unit swizzled
    float* smB  = sm + SA_F;            // 2 stages of [256][32]
    float* smV2 = sm + SA_F + 2 * SB_F; // [4096]

    const int tid  = threadIdx.x;
    const int lane = tid & 31;
    const int wid  = tid >> 5;
    const int g    = lane >> 2;
    const int tig  = lane & 3;
    const int wm   = wid & 1;           // 2 m-warps (64 rows each)
    const int wn   = wid >> 1;          // 4 n-warps (64 cols each)
    const int p0   = blockIdx.x * TILE_M;
    const int swz  = (g & 1) << 2;

    for (int k = tid; k < VOCAB; k += 256) smV2[k] = g_v2[k];

    // A -> smem (resident, cp.async, 32 x 16B per thread)
    {
        uint32_t aB = (uint32_t)__cvta_generic_to_shared(smA);
#pragma unroll
        for (int pp = 0; pp < 32; pp++) {
            int gid = tid + pp * 256;
            int r = gid >> 6, u = gid & 63;
            uint32_t dst = aB + (uint32_t)(r * 1024) + (uint32_t)((u ^ ((r & 1) << 2)) << 4);
            CP_ASYNC16(dst, g_pperm + (p0 + r) * D_DIM + u * 4);
        }
        CP_COMMIT();
    }
    const uint32_t bB = (uint32_t)__cvta_generic_to_shared(smB);
    // B stage 0 (nt=0, kc=0)
    {
#pragma unroll
        for (int rr = 0; rr < 8; rr++) {
            int n = (tid >> 3) + rr * 32;
            int u = tid & 7;
            CP_ASYNC16(bB + (uint32_t)(n * 128) + (uint32_t)((u ^ ((n & 1) << 2)) << 4),
                       g_vperm + n * D_DIM + u * 4);
        }
        CP_COMMIT();
    }

    float b1[8], b2[8];
    int   i1[8], i2[8];
#pragma unroll
    for (int r = 0; r < 8; r++) { b1[r] = 3.4e38f; b2[r] = 3.4e38f; i1[r] = 0; i2[r] = 0; }

#define UPD2(rl, sv, nv) do { \
        float _s = (sv); int _n = (nv); \
        if (_s < b2[rl]) { \
            if (_s < b1[rl]) { b2[rl] = b1[rl]; i2[rl] = i1[rl]; b1[rl] = _s; i1[rl] = _n; } \
            else { b2[rl] = _s; i2[rl] = _n; } \
        } } while (0)

    int s = 0;
    for (int nt = 0; nt < NT; nt++) {
        float acc[4][8][4];
#pragma unroll
        for (int i = 0; i < 4; i++)
#pragma unroll
            for (int j = 0; j < 8; j++)
#pragma unroll
                for (int e = 0; e < 4; e++) acc[i][j][e] = 0.f;

#pragma unroll 1
        for (int kc = 0; kc < KCH; kc++, s++) {
            const int nx = s + 1;
            if (nx < NSTEPS) {
                const int xnt = nx >> 3, xkc = nx & 7;
                const uint32_t dstB = bB + (uint32_t)((nx & 1) * SB_F * 4);
#pragma unroll
                for (int rr = 0; rr < 8; rr++) {
                    int n = (tid >> 3) + rr * 32;
                    int u = tid & 7;
                    CP_ASYNC16(dstB + (uint32_t)(n * 128) + (uint32_t)((u ^ ((n & 1) << 2)) << 4),
                               g_vperm + (xnt * TILE_N + n) * D_DIM + xkc * 32 + u * 4);
                }
                CP_COMMIT();
                asm volatile("cp.async.wait_group 1;" ::: "memory");
            } else {
                asm volatile("cp.async.wait_group 0;" ::: "memory");
            }
            __syncthreads();

            const float* Bb = smB + (s & 1) * SB_F;
#pragma unroll
            for (int kg = 0; kg < 2; kg++) {
                const int grp = kc * 2 + kg;
                const int pu = ((grp * 4 + tig) ^ swz) << 2;
                float4 af[4][2];
#pragma unroll
                for (int i = 0; i < 4; i++) {
                    const int r0 = wm * 64 + i * 16 + g;
                    af[i][0] = *(const float4*)&smA[r0 * 256 + pu];
                    af[i][1] = *(const float4*)&smA[(r0 + 8) * 256 + pu];
                }
                const int pb = ((kg * 4 + tig) ^ swz) << 2;
                float4 bf[8];
#pragma unroll
                for (int j = 0; j < 8; j++) {
                    const int n = wn * 64 + j * 8 + g;
                    bf[j] = *(const float4*)&Bb[n * 32 + pb];
                }
#pragma unroll
                for (int i = 0; i < 4; i++)
#pragma unroll
                    for (int j = 0; j < 8; j++) {
                        mma8(acc[i][j], af[i][0].x, af[i][1].x, af[i][0].y, af[i][1].y,
                             bf[j].x, bf[j].y);
                        mma8(acc[i][j], af[i][0].z, af[i][1].z, af[i][0].w, af[i][1].w,
                             bf[j].z, bf[j].w);
                    }
            }
            __syncthreads();
        }

        // epilogue: approx scores + best2 per owned row
        const int nbase = nt * TILE_N + wn * 64;
#pragma unroll
        for (int j = 0; j < 8; j++) {
            const int n0 = nbase + j * 8 + 2 * tig;
            const float v20 = smV2[n0], v21 = smV2[n0 + 1];
#pragma unroll
            for (int i = 0; i < 4; i++) {
                UPD2(i * 2 + 0, v20 - 2.f * acc[i][j][0], n0);
                UPD2(i * 2 + 0, v21 - 2.f * acc[i][j][1], n0 + 1);
                UPD2(i * 2 + 1, v20 - 2.f * acc[i][j][2], n0);
                UPD2(i * 2 + 1, v21 - 2.f * acc[i][j][3], n0 + 1);
            }
        }
    }

    // dump candidates to smem (reuse B buffers)
    __syncthreads();
    float4* cand = (float4*)smB;   // [128 rows][16 slots]
#pragma unroll
    for (int i = 0; i < 4; i++)
#pragma unroll
        for (int h = 0; h < 2; h++) {
            const int r = wm * 64 + i * 16 + h * 8 + g;
            const int rl = i * 2 + h;
            cand[r * 16 + wn * 4 + tig] =
                make_float4(b1[rl], __int_as_float(i1[rl]), b2[rl], __int_as_float(i2[rl]));
        }
    __syncthreads();

    // exact fp32 rescue: rescore every candidate within m~ + eps
    if (tid < TILE_M) {
        const int r = tid;
        float m = 3.4e38f;
#pragma unroll
        for (int sl = 0; sl < 16; sl++) m = fminf(m, cand[r * 16 + sl].x);
        const float thr = m + 0.75f;
        float bestv = 3.4e38f;
        int   besti = 0x7FFFFFFF;
        const float* pp = patches + (size_t)(p0 + r) * D_DIM;
#pragma unroll 1
        for (int sl = 0; sl < 16; sl++) {
            const float4 cc = cand[r * 16 + sl];
#pragma unroll
            for (int e = 0; e < 2; e++) {
                const float sc = e ? cc.z : cc.x;
                const int   vi = __float_as_int(e ? cc.w : cc.y);
                if (sc <= thr) {
                    const float* vv = vocab + (size_t)vi * D_DIM;
                    float dot = 0.f;
#pragma unroll 8
                    for (int k4 = 0; k4 < 64; k4++) {
                        const float4 a = *(const float4*)(pp + k4 * 4);
                        const float4 b = *(const float4*)(vv + k4 * 4);
                        dot += a.x * b.x; dot += a.y * b.y;
                        dot += a.z * b.z; dot += a.w * b.w;
                    }
                    const float se = smV2[vi] - 2.f * dot;
                    if (se < bestv || (se == bestv && vi < besti)) { bestv = se; besti = vi; }
                }
            }
        }
        tokens[p0 + r] = (float)besti;
    }
}

// ---------------------------------------------------------------------------
extern "C" void kernel_launch(void* const* d_in, const int* in_sizes, int n_in,
                              void* d_out, int out_size) {
    const float* images = (const float*)d_in[0];   // [64, 256, 256]
    const float* vocab  = (const float*)d_in[1];   // [4096, 256]
    float* out = (float*)d_out;

    const int npix = in_sizes[0];                  // 4194304
    const int nvoc = in_sizes[1];                  // 1048576
    const int V  = nvoc / D_DIM;                   // 4096
    const int NP = npix / D_DIM;                   // 16384

    float* patches = out;
    float* tokens  = out + npix;

    v2_kernel<<<(V + 7) / 8, 256>>>(vocab, V);
    vocab_perm_kernel<<<(nvoc + 255) / 256, 256>>>(vocab, nvoc);
    patchify_perm_kernel<<<(npix + 255) / 256, 256>>>(images, patches, npix);

    cudaFuncSetAttribute(vq_mma_kernel, cudaFuncAttributeMaxDynamicSharedMemorySize, SMEM_BYTES);
    vq_mma_kernel<<<NP / TILE_M, 256, SMEM_BYTES>>>(patches, vocab, tokens);
}